// round 7
// baseline (speedup 1.0000x reference)
#include <cuda_runtime.h>
#include <stdint.h>
#include <math.h>

#define DD   20
#define TPB  128
#define WPB  4               // warps per block
#define NCTA 760             // 152 SMs x 5 CTAs
#define HST  24              // h smem row stride (floats)

__device__ double   g_psum[NCTA];
__device__ double   g_pabs[NCTA];
__device__ unsigned g_done = 0;

static __device__ __forceinline__ uint32_t f2tf(float f) {
    uint32_t u; asm("cvt.rna.tf32.f32 %0, %1;" : "=r"(u) : "f"(f)); return u;
}
static __device__ __forceinline__ void mma8(float* c, const uint32_t* a, const uint32_t* b) {
    asm volatile("mma.sync.aligned.m16n8k8.row.col.f32.tf32.tf32.f32 "
        "{%0,%1,%2,%3}, {%4,%5,%6,%7}, {%8,%9}, {%0,%1,%2,%3};"
        : "+f"(c[0]), "+f"(c[1]), "+f"(c[2]), "+f"(c[3])
        : "r"(a[0]), "r"(a[1]), "r"(a[2]), "r"(a[3]), "r"(b[0]), "r"(b[1]));
}
static __device__ __forceinline__ uint32_t s2u(const void* p) {
    uint32_t a;
    asm("{ .reg .u64 t; cvta.to.shared.u64 t, %1; cvt.u32.u64 %0, t; }" : "=r"(a) : "l"(p));
    return a;
}
// per-warp tile prefetch: 2560B = 5 coalesced 16B cp.async per lane
static __device__ __forceinline__ void issue_tile(const char* Xb, long long tile,
                                                  long long ntiles, long long maxoff,
                                                  uint32_t dst, int lane) {
    if (tile >= ntiles) tile = ntiles - 1;
    long long base = tile * 2560 + (long long)lane * 16;
    #pragma unroll
    for (int c = 0; c < 5; c++) {
        long long off = base + c * 512;
        if (off > maxoff) off = maxoff;
        asm volatile("cp.async.cg.shared.global [%0], [%1], 16;"
                     :: "r"(dst + c * 512 + lane * 16), "l"(Xb + off) : "memory");
    }
    asm volatile("cp.async.commit_group;" ::: "memory");
}

__global__ void __launch_bounds__(TPB, 5)
fused_kernel(const float* __restrict__ X, const float* __restrict__ W,
             const float* __restrict__ bvec, const float* __restrict__ Wi,
             long long nrows, float* __restrict__ out) {
    __shared__ float  sW[400], sWi[400], sM1[400], sc1[DD], sb2[DD];
    __shared__ float  sh[WPB][2][16 * HST];              // per-warp h roundtrip
    __shared__ __align__(16) float sX[WPB][2][32 * DD];  // per-warp X double buffer
    __shared__ double s_rs[WPB], s_ra[WPB];
    __shared__ double fs[TPB], fa[TPB];
    __shared__ int    s_last;

    const int t = threadIdx.x;
    const int wid = t >> 5, lane = t & 31;
    const int qr = lane >> 2, qc = lane & 3;

    // ---- stage weights; precompute M1 = W^T @ Wi and c1 = b @ Wi + 1 ----
    for (int i = t; i < 400; i += TPB) { sW[i] = W[i]; sWi[i] = Wi[i]; }
    if (t < DD) sb2[t] = bvec[t];
    __syncthreads();
    for (int e = t; e < 400; e += TPB) {
        int k = e / 20, n = e % 20;
        float a = 0.f;
        #pragma unroll
        for (int j = 0; j < 20; j++) a = fmaf(sW[j*20 + k], sWi[j*20 + n], a);
        sM1[e] = a;
    }
    if (t < DD) {
        float a = 1.f;
        #pragma unroll
        for (int j = 0; j < 20; j++) a = fmaf(sb2[j], sWi[j*20 + t], a);
        sc1[t] = a;
    }
    __syncthreads();

    // ---- constant B fragments (tf32, rna-rounded once) + bias C-inits ----
    uint32_t b1f[3][3][2], b2f[3][3][2];
    float    bi1[3][2], bi2[3][2];
    #pragma unroll
    for (int j = 0; j < 3; j++) {
        int k0 = 8*j + qc, k1 = k0 + 4;
        #pragma unroll
        for (int i = 0; i < 3; i++) {
            int n = 8*i + qr;
            float v0 = (k0 < 20 && n < 20) ? sM1[k0*20 + n] : 0.f;
            float v1 = (k1 < 20 && n < 20) ? sM1[k1*20 + n] : 0.f;
            b1f[j][i][0] = f2tf(v0); b1f[j][i][1] = f2tf(v1);
            float w0 = (k0 < 20 && n < 20) ? sW[n*20 + k0] : 0.f;
            float w1 = (k1 < 20 && n < 20) ? sW[n*20 + k1] : 0.f;
            b2f[j][i][0] = f2tf(w0); b2f[j][i][1] = f2tf(w1);
        }
    }
    #pragma unroll
    for (int i = 0; i < 3; i++) {
        int n0 = 8*i + 2*qc;
        bi1[i][0] = (n0     < 20) ? sc1[n0]     : 0.f;
        bi1[i][1] = (n0 + 1 < 20) ? sc1[n0 + 1] : 0.f;
        bi2[i][0] = (n0     < 20) ? sb2[n0]     : 0.f;
        bi2[i][1] = (n0 + 1 < 20) ? sb2[n0 + 1] : 0.f;
    }

    // ---- mainloop: 32 rows/warp/iter, cp.async double-buffered ----
    const long long ntiles = (nrows + 31) >> 5;
    const long long gw = (long long)blockIdx.x * WPB + wid;
    const long long nw = (long long)gridDim.x * WPB;
    const long long maxoff = nrows * 80 - 16;
    const char* Xb = (const char*)X;
    const uint32_t xs0 = s2u(&sX[wid][0][0]);
    const uint32_t xs1 = s2u(&sX[wid][1][0]);

    float aS0 = 0.f, aS1 = 0.f, aA0 = 0.f, aA1 = 0.f;
    int p = 0;

    if (gw < ntiles) issue_tile(Xb, gw, ntiles, maxoff, xs0, lane);

    for (long long tl = gw; tl < ntiles; tl += nw) {
        issue_tile(Xb, tl + nw, ntiles, maxoff, p ? xs0 : xs1, lane);
        asm volatile("cp.async.wait_group 1;" ::: "memory");
        __syncwarp();

        const float* xs = &sX[wid][p][0];
        const long long Rt = tl << 5;

        // ---- A fragments: raw fp32 bits (HW truncates to tf32) ----
        uint32_t a[2][3][4];
        #pragma unroll
        for (int s = 0; s < 2; s++) {
            const float* q0 = xs + (s*16 + qr) * 20;
            const float* q1 = q0 + 8 * 20;
            #pragma unroll
            for (int j = 0; j < 2; j++) {
                a[s][j][0] = __float_as_uint(q0[8*j + qc]);
                a[s][j][1] = __float_as_uint(q1[8*j + qc]);
                a[s][j][2] = __float_as_uint(q0[8*j + qc + 4]);
                a[s][j][3] = __float_as_uint(q1[8*j + qc + 4]);
            }
            a[s][2][0] = __float_as_uint(q0[16 + qc]);
            a[s][2][1] = __float_as_uint(q1[16 + qc]);
            a[s][2][2] = 0u;
            a[s][2][3] = 0u;
        }

        // ---- stage 1: h = relu(X @ M1 + c1) -> per-warp smem ----
        #pragma unroll
        for (int s = 0; s < 2; s++) {
            float* hw = sh[wid][s];
            #pragma unroll
            for (int i = 0; i < 3; i++) {
                float c[4] = { bi1[i][0], bi1[i][1], bi1[i][0], bi1[i][1] };
                mma8(c, a[s][0], b1f[0][i]);
                mma8(c, a[s][1], b1f[1][i]);
                mma8(c, a[s][2], b1f[2][i]);
                int col = 8*i + 2*qc;
                float2 v0 = make_float2(fmaxf(c[0], 0.f), fmaxf(c[1], 0.f));
                float2 v1 = make_float2(fmaxf(c[2], 0.f), fmaxf(c[3], 0.f));
                *(float2*)&hw[qr*HST + col]       = v0;
                *(float2*)&hw[(qr + 8)*HST + col] = v1;
            }
        }
        __syncwarp();

        // ---- layout conversion: h -> A fragments (raw bits, no cvt) ----
        uint32_t a2[2][3][4];
        #pragma unroll
        for (int s = 0; s < 2; s++) {
            const float* hw = sh[wid][s];
            #pragma unroll
            for (int j = 0; j < 3; j++) {
                a2[s][j][0] = __float_as_uint(hw[qr*HST + 8*j + qc]);
                a2[s][j][1] = __float_as_uint(hw[(qr + 8)*HST + 8*j + qc]);
                a2[s][j][2] = __float_as_uint(hw[qr*HST + 8*j + qc + 4]);
                a2[s][j][3] = __float_as_uint(hw[(qr + 8)*HST + 8*j + qc + 4]);
            }
        }
        __syncwarp();

        // ---- stage 2: h3 = h @ W^T + b; split accumulator chains ----
        #pragma unroll
        for (int s = 0; s < 2; s++) {
            bool v0ok = (Rt + s*16 + qr)     < nrows;
            bool v1ok = (Rt + s*16 + qr + 8) < nrows;
            #pragma unroll
            for (int i = 0; i < 3; i++) {
                float c[4] = { bi2[i][0], bi2[i][1], bi2[i][0], bi2[i][1] };
                mma8(c, a2[s][0], b2f[0][i]);
                mma8(c, a2[s][1], b2f[1][i]);
                mma8(c, a2[s][2], b2f[2][i]);
                if (v0ok) { aS0 += c[0] + c[1]; aA0 += fabsf(c[0]) + fabsf(c[1]); }
                if (v1ok) { aS1 += c[2] + c[3]; aA1 += fabsf(c[2]) + fabsf(c[3]); }
            }
        }
        p ^= 1;
    }
    asm volatile("cp.async.wait_group 0;" ::: "memory");   // drain tail prefetch

    // ---- CTA reduce ----
    float accS = aS0 + aS1, accA = aA0 + aA1;
    #pragma unroll
    for (int o = 16; o > 0; o >>= 1) {
        accS += __shfl_down_sync(0xFFFFFFFFu, accS, o);
        accA += __shfl_down_sync(0xFFFFFFFFu, accA, o);
    }
    if (lane == 0) { s_rs[wid] = (double)accS; s_ra[wid] = (double)accA; }
    __syncthreads();

    if (t == 0) {
        double S = s_rs[0] + s_rs[1] + s_rs[2] + s_rs[3];
        double A = s_ra[0] + s_ra[1] + s_ra[2] + s_ra[3];
        g_psum[blockIdx.x] = S;
        g_pabs[blockIdx.x] = A;
        __threadfence();
        unsigned v = atomicAdd(&g_done, 1u);
        s_last = (v == gridDim.x - 1) ? 1 : 0;
    }
    __syncthreads();

    // ---- last CTA: global reduce + exact halving count + write scalar ----
    if (s_last) {
        __threadfence();
        double S = 0.0, A = 0.0;
        for (int i = t; i < (int)gridDim.x; i += TPB) { S += g_psum[i]; A += g_pabs[i]; }
        fs[t] = S; fa[t] = A;
        __syncthreads();
        for (int o = TPB/2; o > 0; o >>= 1) {
            if (t < o) { fs[t] += fs[t + o]; fa[t] += fa[t + o]; }
            __syncthreads();
        }
        if (t == 0) {
            float s = (float)fa[0];
            int k = 0;
            while (s > 1.0f && k < 300) { s *= 0.5f; k++; }
            out[0] = (float)ldexp(fs[0], -k);   // sum(h) * 2^-k (exact scale)
            __threadfence();
            g_done = 0;                          // reset for next graph replay
        }
    }
}

// ---------------- launch ----------------
extern "C" void kernel_launch(void* const* d_in, const int* in_sizes, int n_in,
                              void* d_out, int out_size) {
    const float* X  = (const float*)d_in[0];
    const float* W  = (const float*)d_in[1];
    const float* b  = (const float*)d_in[2];
    const float* Wi = (const float*)d_in[3];

    long long nrows = (long long)in_sizes[0] / DD;

    fused_kernel<<<NCTA, TPB>>>(X, W, b, Wi, nrows, (float*)d_out);
}